// round 3
// baseline (speedup 1.0000x reference)
#include <cuda_runtime.h>

// Fused persistent LSTM + MLP classifier. (Identical design to R1/R2 —
// both prior rounds died in GPU-broker container acquisition before the
// kernel was ever compiled; no kernel-side evidence exists to react to.)
//
// One kernel, 128 blocks x 128 threads, 8 batch rows per block.
// Combined weight Wc = [W_hh | W_ih] (256 x 114) lives in SMEM for the whole
// kernel; h and x_t live in a shared "activation" vector act[k][row]
// (k<64: h, k>=64: x_t). c lives in registers of the owning thread.
// Per step: gates = act @ Wc^T + bias  (register-tiled 4x4 micro-GEMM),
// then elementwise LSTM cell update; final 2-layer MLP head at the end.

namespace {

constexpr int Bn   = 1024;
constexpr int Sn   = 512;
constexpr int In   = 50;
constexpr int Hn   = 64;
constexpr int G4   = 4 * Hn;     // 256 gates
constexpr int F1n  = 32;
constexpr int Cn   = 2;
constexpr int KTOT = Hn + In;    // 114
constexpr int TB   = 8;          // batch rows per block
constexpr int GRID = Bn / TB;    // 128 blocks
constexpr int NT   = 128;        // threads per block

struct Smem {
  float Wc[KTOT][G4];    // [k][gate]   116736 B
  float act[KTOT][TB];   // [k][row]      3648 B  (k<64: h, k>=64: x_t)
  float gates[TB][G4];   //               8192 B
  float bias[G4];        //               1024 B
  float f1[TB][F1n];     //               1024 B
};                       // total ~130624 B < 227 KB dynamic smem

__device__ __forceinline__ float tanh_ap(float x) {
  float y;
  asm("tanh.approx.f32 %0, %1;" : "=f"(y) : "f"(x));
  return y;
}
__device__ __forceinline__ float sigmoid_ap(float x) {
  return fmaf(0.5f, tanh_ap(0.5f * x), 0.5f);
}

__global__ __launch_bounds__(NT, 1) void lstm_fused(
    const float* __restrict__ x,
    const float* __restrict__ W_ih, const float* __restrict__ W_hh,
    const float* __restrict__ b_ih, const float* __restrict__ b_hh,
    const float* __restrict__ W1,   const float* __restrict__ b1,
    const float* __restrict__ W2,   const float* __restrict__ b2,
    float* __restrict__ out) {
  extern __shared__ unsigned char smem_raw[];
  Smem& s = *reinterpret_cast<Smem*>(smem_raw);

  const int tid  = threadIdx.x;
  const int row0 = blockIdx.x * TB;

  // ---- init: combined weights, bias, initial activations ----
  for (int idx = tid; idx < KTOT * G4; idx += NT) {
    int k = idx / G4, g = idx - k * G4;
    s.Wc[k][g] = (k < Hn) ? W_hh[g * Hn + k] : W_ih[g * In + (k - Hn)];
  }
  for (int g = tid; g < G4; g += NT) s.bias[g] = b_ih[g] + b_hh[g];
  for (int idx = tid; idx < Hn * TB; idx += NT)   // h part of act = 0
    (&s.act[0][0])[idx] = 0.0f;

  // t-invariant x-prefetch slot assignment: TB*In = 400 slots over 128 thr x 4
  int  xr_row[4], xr_i[4];
  bool xr_ok[4];
  const float* xr_ptr[4];
#pragma unroll
  for (int j = 0; j < 4; j++) {
    int idx   = tid + NT * j;
    xr_ok[j]  = (idx < TB * In);
    int r     = idx / In;
    int i     = idx - r * In;
    if (!xr_ok[j]) { r = 0; i = 0; }
    xr_row[j] = r;
    xr_i[j]   = i;
    xr_ptr[j] = x + (long)(row0 + r) * (Sn * In) + i;
  }
#pragma unroll
  for (int j = 0; j < 4; j++)                     // x for t=0
    if (xr_ok[j]) s.act[Hn + xr_i[j]][xr_row[j]] = xr_ptr[j][0];

  __syncthreads();

  const int gq = tid & 63;   // gate quad id (gates gq*4..gq*4+3)
  const int rg = tid >> 6;   // row group (rows rg*4..rg*4+3)
  const float4 bias4 = *reinterpret_cast<const float4*>(&s.bias[gq * 4]);

  float c[4] = {0.f, 0.f, 0.f, 0.f};

  for (int t = 0; t < Sn; t++) {
    // prefetch next step's x early (hidden under the GEMM below)
    float xr[4];
    const bool havex = (t + 1 < Sn);
    if (havex) {
#pragma unroll
      for (int j = 0; j < 4; j++)
        if (xr_ok[j]) xr[j] = xr_ptr[j][(t + 1) * In];
    }

    // ---- gate micro-GEMM: 4 rows x 4 gates per thread over K=114 ----
    float acc[4][4];
#pragma unroll
    for (int rr = 0; rr < 4; rr++) {
      acc[rr][0] = bias4.x; acc[rr][1] = bias4.y;
      acc[rr][2] = bias4.z; acc[rr][3] = bias4.w;
    }
#pragma unroll 6
    for (int k = 0; k < KTOT; k++) {
      const float4 w = *reinterpret_cast<const float4*>(&s.Wc[k][gq * 4]);
      const float4 a = *reinterpret_cast<const float4*>(&s.act[k][rg * 4]);
      acc[0][0] = fmaf(a.x, w.x, acc[0][0]);
      acc[0][1] = fmaf(a.x, w.y, acc[0][1]);
      acc[0][2] = fmaf(a.x, w.z, acc[0][2]);
      acc[0][3] = fmaf(a.x, w.w, acc[0][3]);
      acc[1][0] = fmaf(a.y, w.x, acc[1][0]);
      acc[1][1] = fmaf(a.y, w.y, acc[1][1]);
      acc[1][2] = fmaf(a.y, w.z, acc[1][2]);
      acc[1][3] = fmaf(a.y, w.w, acc[1][3]);
      acc[2][0] = fmaf(a.z, w.x, acc[2][0]);
      acc[2][1] = fmaf(a.z, w.y, acc[2][1]);
      acc[2][2] = fmaf(a.z, w.z, acc[2][2]);
      acc[2][3] = fmaf(a.z, w.w, acc[2][3]);
      acc[3][0] = fmaf(a.w, w.x, acc[3][0]);
      acc[3][1] = fmaf(a.w, w.y, acc[3][1]);
      acc[3][2] = fmaf(a.w, w.z, acc[3][2]);
      acc[3][3] = fmaf(a.w, w.w, acc[3][3]);
    }
#pragma unroll
    for (int rr = 0; rr < 4; rr++) {
      float4 v = make_float4(acc[rr][0], acc[rr][1], acc[rr][2], acc[rr][3]);
      *reinterpret_cast<float4*>(&s.gates[rg * 4 + rr][gq * 4]) = v;
    }
    __syncthreads();

    // ---- elementwise LSTM cell: 512 (row,unit) pairs, 4 per thread ----
#pragma unroll
    for (int j = 0; j < 4; j++) {
      const int idx = tid + NT * j;
      const int row = idx >> 6;
      const int u   = idx & 63;
      const float ig = sigmoid_ap(s.gates[row][u]);
      const float fg = sigmoid_ap(s.gates[row][Hn + u]);
      const float gg = tanh_ap(s.gates[row][2 * Hn + u]);
      const float og = sigmoid_ap(s.gates[row][3 * Hn + u]);
      c[j] = fmaf(fg, c[j], ig * gg);
      s.act[u][row] = og * tanh_ap(c[j]);
    }
    if (havex) {
#pragma unroll
      for (int j = 0; j < 4; j++)
        if (xr_ok[j]) s.act[Hn + xr_i[j]][xr_row[j]] = xr[j];
    }
    __syncthreads();
  }

  // ---- classifier head: h_last (in s.act[u][row]) -> F1 -> C ----
#pragma unroll
  for (int j = 0; j < 2; j++) {
    const int idx = tid + NT * j;          // TB*F1 = 256 outputs
    const int row = idx >> 5;
    const int f   = idx & 31;
    float a1 = b1[f];
#pragma unroll
    for (int u = 0; u < Hn; u++) a1 = fmaf(s.act[u][row], W1[f * Hn + u], a1);
    s.f1[row][f] = fmaxf(a1, 0.0f);
  }
  __syncthreads();
  if (tid < TB * Cn) {
    const int row = tid >> 1;
    const int cl  = tid & 1;
    float o = b2[cl];
#pragma unroll
    for (int f = 0; f < F1n; f++) o = fmaf(s.f1[row][f], W2[cl * F1n + f], o);
    out[(row0 + row) * Cn + cl] = o;
  }
}

}  // namespace

extern "C" void kernel_launch(void* const* d_in, const int* in_sizes, int n_in,
                              void* d_out, int out_size) {
  (void)in_sizes; (void)n_in; (void)out_size;
  const float* x    = (const float*)d_in[0];
  const float* W_ih = (const float*)d_in[1];
  const float* W_hh = (const float*)d_in[2];
  const float* b_ih = (const float*)d_in[3];
  const float* b_hh = (const float*)d_in[4];
  const float* W1   = (const float*)d_in[5];
  const float* b1   = (const float*)d_in[6];
  const float* W2   = (const float*)d_in[7];
  const float* b2   = (const float*)d_in[8];
  float* out = (float*)d_out;

  cudaFuncSetAttribute(lstm_fused, cudaFuncAttributeMaxDynamicSharedMemorySize,
                       (int)sizeof(Smem));
  lstm_fused<<<GRID, NT, sizeof(Smem)>>>(x, W_ih, W_hh, b_ih, b_hh,
                                         W1, b1, W2, b2, out);
}

// round 4
// speedup vs baseline: 1.0710x; 1.0710x over previous
#include <cuda_runtime.h>

// Fused persistent LSTM + MLP classifier, v2.
// R3 evidence: issue=52%, occ=6.2% (1 warp/SMSP), fma=36.6% -> issue/latency
// bound, not FMA-pipe bound. v2: (a) fma.rn.f32x2 packed math (FFMA2, full
// 128-lane FP32 rate), (b) NT=256 with K split in half per thread ->
// 2 warps/SMSP, (c) all row-pairs kept as f32x2 end-to-end (GEMM accumulators,
// gate partial buffers, cell state c, h stores) so no per-k packing of the
// activation operand is needed.
//
// grid=128 blocks (8 batch rows each), 256 threads:
//   GEMM phase: thread = (gp in [0,128): gates 2gp,2gp+1) x (kh in {0,1}).
//     acc2[rowpair 4][gate 2] f32x2 over its K half; partials -> smem part[kh].
//   Cell phase: threads 0..127: thread = (up in [0,32): units 2up,2up+1) x
//     (rp in [0,4): rows 2rp,2rp+1); reads part[0]+part[1] coalesced LDS.128.

namespace {

constexpr int Bn   = 1024;
constexpr int Sn   = 512;
constexpr int In   = 50;
constexpr int Hn   = 64;
constexpr int G4   = 4 * Hn;     // 256 gates
constexpr int F1n  = 32;
constexpr int Cn   = 2;
constexpr int KTOT = Hn + In;    // 114
constexpr int KH0  = 57;         // kh=0: k in [0,57), kh=1: [57,114)
constexpr int TB   = 8;
constexpr int GRID = Bn / TB;    // 128
constexpr int NT   = 256;

struct Smem {
  float Wc[KTOT][G4];        // [k][gate]                     116736 B
  float act[KTOT][TB];       // [k][row] (k<64: h, else x_t)    3648 B
  float part[2][4][128][4];  // [kh][rp][gp][{g0r0,g0r1,g1r0,g1r1}] 16384 B
  float bias[G4];            //                                 1024 B
  float f1[TB][F1n];         //                                 1024 B
};                           // 138816 B < 227 KB

using u64 = unsigned long long;

__device__ __forceinline__ u64 pack2(float lo, float hi) {
  u64 r;
  asm("mov.b64 %0, {%1, %2};" : "=l"(r)
      : "r"(__float_as_uint(lo)), "r"(__float_as_uint(hi)));
  return r;
}
__device__ __forceinline__ void unpack2(u64 v, float& lo, float& hi) {
  unsigned a, b;
  asm("mov.b64 {%0, %1}, %2;" : "=r"(a), "=r"(b) : "l"(v));
  lo = __uint_as_float(a);
  hi = __uint_as_float(b);
}
__device__ __forceinline__ u64 fma2(u64 a, u64 b, u64 c) {
  u64 d;
  asm("fma.rn.f32x2 %0, %1, %2, %3;" : "=l"(d) : "l"(a), "l"(b), "l"(c));
  return d;
}
__device__ __forceinline__ u64 add2(u64 a, u64 b) {
  u64 d;
  asm("add.rn.f32x2 %0, %1, %2;" : "=l"(d) : "l"(a), "l"(b));
  return d;
}

__device__ __forceinline__ float tanh_ap(float x) {
  float y;
  asm("tanh.approx.f32 %0, %1;" : "=f"(y) : "f"(x));
  return y;
}
__device__ __forceinline__ float sigmoid_ap(float x) {
  return fmaf(0.5f, tanh_ap(0.5f * x), 0.5f);
}

__global__ __launch_bounds__(NT, 1) void lstm_fused(
    const float* __restrict__ x,
    const float* __restrict__ W_ih, const float* __restrict__ W_hh,
    const float* __restrict__ b_ih, const float* __restrict__ b_hh,
    const float* __restrict__ W1,   const float* __restrict__ b1,
    const float* __restrict__ W2,   const float* __restrict__ b2,
    float* __restrict__ out) {
  extern __shared__ unsigned char smem_raw[];
  Smem& s = *reinterpret_cast<Smem*>(smem_raw);

  const int tid  = threadIdx.x;
  const int row0 = blockIdx.x * TB;

  // ---- init ----
  for (int idx = tid; idx < KTOT * G4; idx += NT) {
    int k = idx / G4, g = idx - k * G4;
    s.Wc[k][g] = (k < Hn) ? W_hh[g * Hn + k] : W_ih[g * In + (k - Hn)];
  }
  for (int g = tid; g < G4; g += NT) s.bias[g] = b_ih[g] + b_hh[g];
  for (int idx = tid; idx < Hn * TB; idx += NT)   // h part of act = 0
    (&s.act[0][0])[idx] = 0.0f;

  // t-invariant x-prefetch slots: TB*In = 400 over 256 thr x 2
  int  xr_i2[2], xr_row2[2];
  bool xr_ok[2];
  const float* xr_ptr[2];
#pragma unroll
  for (int j = 0; j < 2; j++) {
    int idx   = tid + NT * j;
    xr_ok[j]  = (idx < TB * In);
    int r     = idx / In;
    int i     = idx - r * In;
    if (!xr_ok[j]) { r = 0; i = 0; }
    xr_row2[j] = r;
    xr_i2[j]   = i;
    xr_ptr[j]  = x + (long)(row0 + r) * (Sn * In) + i;
  }
#pragma unroll
  for (int j = 0; j < 2; j++)                     // x for t=0
    if (xr_ok[j]) s.act[Hn + xr_i2[j]][xr_row2[j]] = xr_ptr[j][0];

  __syncthreads();

  // GEMM role
  const int gp = tid & 127;          // gates 2gp, 2gp+1
  const int kh = tid >> 7;           // K half
  const int k0 = kh ? KH0 : 0;
  const int k1 = kh ? KTOT : KH0;
  u64 bias2[2];
#pragma unroll
  for (int g = 0; g < 2; g++) {
    float b = (kh == 0) ? s.bias[2 * gp + g] : 0.0f;
    bias2[g] = pack2(b, b);
  }

  // Cell role (threads 0..127): units 2up,2up+1 x rows 2rp,2rp+1
  const int up = tid >> 2;           // 0..31 (valid when tid<128)
  const int rp = tid & 3;
  u64 c2[2] = {0ull, 0ull};          // c packed {row even, row odd} per unit

  for (int t = 0; t < Sn; t++) {
    // prefetch next x (hidden under GEMM)
    float xv[2];
    const bool havex = (t + 1 < Sn);
    if (havex) {
#pragma unroll
      for (int j = 0; j < 2; j++)
        if (xr_ok[j]) xv[j] = xr_ptr[j][(t + 1) * In];
    }

    // ---- GEMM: 2 gates x 8 rows over this thread's K half ----
    u64 acc[4][2];
#pragma unroll
    for (int r = 0; r < 4; r++) { acc[r][0] = bias2[0]; acc[r][1] = bias2[1]; }

#pragma unroll 3
    for (int k = k0; k < k1; k++) {
      const float2 w = *reinterpret_cast<const float2*>(&s.Wc[k][2 * gp]);
      const ulonglong2 aa =
          *reinterpret_cast<const ulonglong2*>(&s.act[k][0]);  // rows 0-3
      const ulonglong2 ab =
          *reinterpret_cast<const ulonglong2*>(&s.act[k][4]);  // rows 4-7
      const u64 w0 = pack2(w.x, w.x);
      const u64 w1 = pack2(w.y, w.y);
      acc[0][0] = fma2(aa.x, w0, acc[0][0]);
      acc[0][1] = fma2(aa.x, w1, acc[0][1]);
      acc[1][0] = fma2(aa.y, w0, acc[1][0]);
      acc[1][1] = fma2(aa.y, w1, acc[1][1]);
      acc[2][0] = fma2(ab.x, w0, acc[2][0]);
      acc[2][1] = fma2(ab.x, w1, acc[2][1]);
      acc[3][0] = fma2(ab.y, w0, acc[3][0]);
      acc[3][1] = fma2(ab.y, w1, acc[3][1]);
    }
    // store partials (coalesced STS.128)
#pragma unroll
    for (int r = 0; r < 4; r++) {
      ulonglong2 v;
      v.x = acc[r][0];
      v.y = acc[r][1];
      *reinterpret_cast<ulonglong2*>(&s.part[kh][r][gp][0]) = v;
    }
    __syncthreads();

    // ---- cell update (threads 0..127) ----
    if (tid < 128) {
      u64 gs[4][2];  // [q = i/f/g/o][unit 0/1], each {row even, row odd}
#pragma unroll
      for (int q = 0; q < 4; q++) {
        const int gq = up + 32 * q;
        const ulonglong2 p0 =
            *reinterpret_cast<const ulonglong2*>(&s.part[0][rp][gq][0]);
        const ulonglong2 p1 =
            *reinterpret_cast<const ulonglong2*>(&s.part[1][rp][gq][0]);
        gs[q][0] = add2(p0.x, p1.x);
        gs[q][1] = add2(p0.y, p1.y);
      }
#pragma unroll
      for (int su = 0; su < 2; su++) {
        float i0, i1, f0, f1, g0, g1, o0, o1, ca, cb;
        unpack2(gs[0][su], i0, i1);
        unpack2(gs[1][su], f0, f1);
        unpack2(gs[2][su], g0, g1);
        unpack2(gs[3][su], o0, o1);
        unpack2(c2[su], ca, cb);
        i0 = sigmoid_ap(i0); i1 = sigmoid_ap(i1);
        f0 = sigmoid_ap(f0); f1 = sigmoid_ap(f1);
        g0 = tanh_ap(g0);    g1 = tanh_ap(g1);
        o0 = sigmoid_ap(o0); o1 = sigmoid_ap(o1);
        ca = fmaf(f0, ca, i0 * g0);
        cb = fmaf(f1, cb, i1 * g1);
        c2[su] = pack2(ca, cb);
        const float h0 = o0 * tanh_ap(ca);
        const float h1 = o1 * tanh_ap(cb);
        // h rows (2rp, 2rp+1) of unit 2up+su  -> 8B-aligned STS.64
        *reinterpret_cast<float2*>(&s.act[2 * up + su][2 * rp]) =
            make_float2(h0, h1);
      }
    }
    if (havex) {
#pragma unroll
      for (int j = 0; j < 2; j++)
        if (xr_ok[j]) s.act[Hn + xr_i2[j]][xr_row2[j]] = xv[j];
    }
    __syncthreads();
  }

  // ---- classifier head: h_last (act[u][row]) -> F1 -> C ----
  {
    const int row = tid >> 5;        // 256 threads = TB*F1 outputs
    const int f   = tid & 31;
    float a1 = b1[f];
#pragma unroll
    for (int u = 0; u < Hn; u++) a1 = fmaf(s.act[u][row], W1[f * Hn + u], a1);
    s.f1[row][f] = fmaxf(a1, 0.0f);
  }
  __syncthreads();
  if (tid < TB * Cn) {
    const int row = tid >> 1;
    const int cl  = tid & 1;
    float o = b2[cl];
#pragma unroll
    for (int f = 0; f < F1n; f++) o = fmaf(s.f1[row][f], W2[cl * F1n + f], o);
    out[(row0 + row) * Cn + cl] = o;
  }
}

}  // namespace

extern "C" void kernel_launch(void* const* d_in, const int* in_sizes, int n_in,
                              void* d_out, int out_size) {
  (void)in_sizes; (void)n_in; (void)out_size;
  const float* x    = (const float*)d_in[0];
  const float* W_ih = (const float*)d_in[1];
  const float* W_hh = (const float*)d_in[2];
  const float* b_ih = (const float*)d_in[3];
  const float* b_hh = (const float*)d_in[4];
  const float* W1   = (const float*)d_in[5];
  const float* b1   = (const float*)d_in[6];
  const float* W2   = (const float*)d_in[7];
  const float* b2   = (const float*)d_in[8];
  float* out = (float*)d_out;

  cudaFuncSetAttribute(lstm_fused, cudaFuncAttributeMaxDynamicSharedMemorySize,
                       (int)sizeof(Smem));
  lstm_fused<<<GRID, NT, sizeof(Smem)>>>(x, W_ih, W_hh, b_ih, b_hh,
                                         W1, b1, W2, b2, out);
}